// round 9
// baseline (speedup 1.0000x reference)
#include <cuda_runtime.h>
#include <cuda_bf16.h>
#include <cstdint>

#define NCLS 10
#define TPB 512
#define NBLOCKS 296          // 148 SMs x 2 blocks: one wave
#define TILE 512             // samples per pipeline stage = TPB (1/thread)
#define STAGES 4
#define X_BYTES (TILE * NCLS * 4)          // 20480
#define T_BYTES (TILE * 4)                 // 2048
#define STAGE_BYTES (X_BYTES + T_BYTES)    // 22528 (16B multiple)
#define SMEM_DATA_OFF 128                  // mbarriers live below
#define SMEM_TOTAL (SMEM_DATA_OFF + STAGES * STAGE_BYTES)  // 90240

// Scratch for deterministic single-kernel reduction (no cudaMalloc allowed).
__device__ float g_partials[NBLOCKS];
__device__ int   g_counter = 0;

// ---------------------------------------------------------------------------
// Anchor table is a fixed constant of this problem (hardcoded in reference).
// Row c = [0, u_c, ~0.., b_c@c, u_c..]; cols 2..c-1 are ~1e-16 (dropped).
// Row 1 = e0 exactly. Coefficients PRE-SCALED by 1/|emb_c| so dots[c] is the
// normalized cosine numerator directly (argmax on scaled dots can disagree
// with raw argmax only within the ~0.2% norm spread -> mean impact ~1e-6).
// ---------------------------------------------------------------------------
#define U0p 0.33333334f
#define U2p (-0.11796222f)
#define U3p (-0.13400556f)
#define U4p (-0.15401756f)
#define U5p (-0.18290730f)
#define U6p (-0.22400673f)
#define U7p (-0.28892502f)
#define U8p (-0.40824831f)
#define U9p (-0.70710677f)
#define B2p 0.94269806f
#define B3p 0.93503881f
#define B4p 0.92610556f
#define B5p 0.91253746f
#define B6p 0.89402682f
#define B7p 0.86577535f
#define B8p 0.81649661f
#define B9p 0.70710677f

__device__ __forceinline__ uint32_t smem_u32(const void* p) {
    uint32_t a;
    asm("{ .reg .u64 t; cvta.to.shared.u64 t, %1; cvt.u32.u64 %0, t; }"
        : "=r"(a) : "l"(p));
    return a;
}

__device__ __forceinline__ float sample_loss(const float x[NCLS], int tgt)
{
    float d[NCLS];
    float w = x[1];
    d[9] = fmaf(U9p, w, B9p * x[9]); w += x[9];
    d[8] = fmaf(U8p, w, B8p * x[8]); w += x[8];
    d[7] = fmaf(U7p, w, B7p * x[7]); w += x[7];
    d[6] = fmaf(U6p, w, B6p * x[6]); w += x[6];
    d[5] = fmaf(U5p, w, B5p * x[5]); w += x[5];
    d[4] = fmaf(U4p, w, B4p * x[4]); w += x[4];
    d[3] = fmaf(U3p, w, B3p * x[3]); w += x[3];
    d[2] = fmaf(U2p, w, B2p * x[2]); w += x[2];
    d[0] = U0p * w;
    d[1] = x[0];                           // row1 = e0, |e0| = 1

    float nsq = 0.f;
#pragma unroll
    for (int k = 0; k < NCLS; k++) nsq = fmaf(x[k], x[k], nsq);
    const float inv1 = rsqrtf(nsq);

    float m[NCLS];
    float adot = d[0];
#pragma unroll
    for (int c = 0; c < NCLS; c++) {
        const bool p = (tgt == c);
        m[c] = p ? -1e30f : d[c];
        if (c > 0) adot = p ? d[c] : adot;
    }
    const float m01 = fmaxf(m[0], m[1]), m23 = fmaxf(m[2], m[3]);
    const float m45 = fmaxf(m[4], m[5]), m67 = fmaxf(m[6], m[7]);
    const float m89 = fmaxf(m[8], m[9]);
    const float best = fmaxf(fmaxf(fmaxf(m01, m23), fmaxf(m45, m67)), m89);

    return fmaxf(fmaf(best, inv1, -0.5f), 0.f) +
           fmaxf(fmaf(-adot, inv1, 0.5f), 0.f);
}

__global__ __launch_bounds__(TPB, 2)
void margin_loss_kernel(const float* __restrict__ x1,
                        const int*   __restrict__ target,
                        int B, float invB, float* __restrict__ out)
{
    extern __shared__ char smem[];
    const int tid = threadIdx.x;
    const uint32_t smem_base = smem_u32(smem);

    // STAGES mbarriers at offsets 0,8,16,24 (tx-count completion, 1 arrival).
    if (tid == 0) {
#pragma unroll
        for (int s = 0; s < STAGES; s++)
            asm volatile("mbarrier.init.shared.b64 [%0], 1;"
                         :: "r"(smem_base + s * 8) : "memory");
    }
    __syncthreads();

    const int nTiles = B / TILE;
    const int nLocal = (blockIdx.x < nTiles)
                       ? (nTiles - blockIdx.x - 1) / gridDim.x + 1 : 0;

    // Prologue: fill pipeline.
    if (tid == 0) {
        const int pre = nLocal < STAGES ? nLocal : STAGES;
        for (int k = 0; k < pre; k++) {
            const int g = blockIdx.x + k * gridDim.x;   // global tile id
            const uint32_t mb = smem_base + k * 8;
            const uint32_t xd = smem_base + SMEM_DATA_OFF + k * STAGE_BYTES;
            asm volatile("mbarrier.arrive.expect_tx.shared.b64 _, [%0], %1;"
                         :: "r"(mb), "r"((uint32_t)STAGE_BYTES) : "memory");
            asm volatile("cp.async.bulk.shared::cta.global.mbarrier::complete_tx::bytes [%0], [%1], %2, [%3];"
                         :: "r"(xd), "l"(x1 + (size_t)g * TILE * NCLS),
                            "r"((uint32_t)X_BYTES), "r"(mb) : "memory");
            asm volatile("cp.async.bulk.shared::cta.global.mbarrier::complete_tx::bytes [%0], [%1], %2, [%3];"
                         :: "r"(xd + X_BYTES), "l"(target + (size_t)g * TILE),
                            "r"((uint32_t)T_BYTES), "r"(mb) : "memory");
        }
    }

    float acc = 0.f;

    for (int k = 0; k < nLocal; k++) {
        const int s  = k & (STAGES - 1);
        const uint32_t ph = (uint32_t)((k / STAGES) & 1);
        const uint32_t mb = smem_base + s * 8;

        // Acquire-wait for stage data.
        asm volatile(
            "{\n\t.reg .pred P;\n"
            "WLP_%=:\n\t"
            "mbarrier.try_wait.parity.acquire.cta.shared::cta.b64 P, [%0], %1, 0x989680;\n\t"
            "@P bra.uni WDN_%=;\n\t"
            "bra.uni WLP_%=;\n"
            "WDN_%=:\n\t}"
            :: "r"(mb), "r"(ph) : "memory");

        // One sample per thread: 40B contiguous at 40*tid (8-aligned always;
        // NOT 16-aligned for odd tid -> must use LDS.64). Bank-check: base
        // word 10*l mod 32 distinct+even per 16-lane phase -> conflict-free.
        const char* xsm = smem + SMEM_DATA_OFF + s * STAGE_BYTES + 40 * tid;
        const float2* xp = reinterpret_cast<const float2*>(xsm);
        const float2 v0 = xp[0], v1 = xp[1], v2 = xp[2], v3 = xp[3], v4 = xp[4];
        const int tgt = *reinterpret_cast<const int*>(
            smem + SMEM_DATA_OFF + s * STAGE_BYTES + X_BYTES + 4 * tid);

        const float x[NCLS] = {v0.x, v0.y, v1.x, v1.y, v2.x,
                               v2.y, v3.x, v3.y, v4.x, v4.y};
        acc += sample_loss(x, tgt);

        // All threads done with stage s -> safe to refill.
        __syncthreads();
        if (tid == 0 && k + STAGES < nLocal) {
            const int g = blockIdx.x + (k + STAGES) * gridDim.x;
            const uint32_t xd = smem_base + SMEM_DATA_OFF + s * STAGE_BYTES;
            asm volatile("mbarrier.arrive.expect_tx.shared.b64 _, [%0], %1;"
                         :: "r"(mb), "r"((uint32_t)STAGE_BYTES) : "memory");
            asm volatile("cp.async.bulk.shared::cta.global.mbarrier::complete_tx::bytes [%0], [%1], %2, [%3];"
                         :: "r"(xd), "l"(x1 + (size_t)g * TILE * NCLS),
                            "r"((uint32_t)X_BYTES), "r"(mb) : "memory");
            asm volatile("cp.async.bulk.shared::cta.global.mbarrier::complete_tx::bytes [%0], [%1], %2, [%3];"
                         :: "r"(xd + X_BYTES), "l"(target + (size_t)g * TILE),
                            "r"((uint32_t)T_BYTES), "r"(mb) : "memory");
        }
    }

    // Tail: B - nTiles*TILE samples (256 for B=4M), direct global loads.
    const int base = nTiles * TILE;
    const int rem  = B - base;
    if (blockIdx.x == 0 && tid < rem) {
        const float* xr = x1 + (size_t)(base + tid) * NCLS;
        float xt[NCLS];
        const float2* xp = reinterpret_cast<const float2*>(xr);
        const float2 v0 = xp[0], v1 = xp[1], v2 = xp[2], v3 = xp[3], v4 = xp[4];
        xt[0]=v0.x; xt[1]=v0.y; xt[2]=v1.x; xt[3]=v1.y; xt[4]=v2.x;
        xt[5]=v2.y; xt[6]=v3.x; xt[7]=v3.y; xt[8]=v4.x; xt[9]=v4.y;
        acc += sample_loss(xt, target[base + tid]);
    }

    // Deterministic block reduction.
    __shared__ float red[TPB];
    red[tid] = acc;
    __syncthreads();
#pragma unroll
    for (int s = TPB / 2; s > 0; s >>= 1) {
        if (tid < s) red[tid] += red[tid + s];
        __syncthreads();
    }

    // Fused final reduction: last block sums partials in fixed order.
    __shared__ bool s_last;
    if (tid == 0) {
        g_partials[blockIdx.x] = red[0];
        __threadfence();
        const int old = atomicAdd(&g_counter, 1);
        s_last = (old == NBLOCKS - 1);
    }
    __syncthreads();

    if (s_last) {
        __threadfence();
        float a = (tid < NBLOCKS) ? g_partials[tid] : 0.f;
        red[tid] = a;
        __syncthreads();
#pragma unroll
        for (int s = TPB / 2; s > 0; s >>= 1) {
            if (tid < s) red[tid] += red[tid + s];
            __syncthreads();
        }
        if (tid == 0) {
            g_counter = 0;          // reset for graph replay
            out[0] = red[0] * invB;
        }
    }
}

extern "C" void kernel_launch(void* const* d_in, const int* in_sizes, int n_in,
                              void* d_out, int out_size)
{
    const float* x1     = (const float*)d_in[0];
    const int*   target = (const int*)  d_in[1];
    float* out = (float*)d_out;

    const int B = in_sizes[0] / NCLS;

    static bool attr_set = false;
    if (!attr_set) {
        cudaFuncSetAttribute(margin_loss_kernel,
                             cudaFuncAttributeMaxDynamicSharedMemorySize,
                             SMEM_TOTAL);
        attr_set = true;
    }

    margin_loss_kernel<<<NBLOCKS, TPB, SMEM_TOTAL>>>(x1, target, B,
                                                     1.0f / (float)B, out);
}

// round 10
// speedup vs baseline: 1.0490x; 1.0490x over previous
#include <cuda_runtime.h>
#include <cuda_bf16.h>
#include <cstdint>

#define NCLS 10
#define TPB 512
#define NBLOCKS 296          // 148 SMs x 2 blocks: one wave
#define TILE 512             // samples per pipeline stage = TPB (1/thread)
#define STAGES 4
#define X_BYTES (TILE * NCLS * 4)          // 20480
#define T_BYTES (TILE * 4)                 // 2048
#define STAGE_BYTES (X_BYTES + T_BYTES)    // 22528 (16B multiple)
#define SMEM_DATA_OFF 128                  // mbarriers live below
#define SMEM_TOTAL (SMEM_DATA_OFF + STAGES * STAGE_BYTES)  // 90240

// Scratch for deterministic single-kernel reduction (no cudaMalloc allowed).
__device__ float g_partials[NBLOCKS];
__device__ int   g_counter = 0;

// ---------------------------------------------------------------------------
// Anchor table is a fixed constant of this problem (hardcoded in reference).
// Row c = [0, u_c, ~0.., b_c@c, u_c..]; cols 2..c-1 are ~1e-16 (dropped).
// Row 1 = e0 exactly. Coefficients PRE-SCALED by 1/|emb_c| so dots[c] is the
// normalized cosine numerator directly (argmax on scaled dots can disagree
// with raw argmax only within the ~0.2% norm spread -> mean impact ~1e-6).
// ---------------------------------------------------------------------------
#define U0p 0.33333334f
#define U2p (-0.11796222f)
#define U3p (-0.13400556f)
#define U4p (-0.15401756f)
#define U5p (-0.18290730f)
#define U6p (-0.22400673f)
#define U7p (-0.28892502f)
#define U8p (-0.40824831f)
#define U9p (-0.70710677f)
#define B2p 0.94269806f
#define B3p 0.93503881f
#define B4p 0.92610556f
#define B5p 0.91253746f
#define B6p 0.89402682f
#define B7p 0.86577535f
#define B8p 0.81649661f
#define B9p 0.70710677f

__device__ __forceinline__ uint32_t smem_u32(const void* p) {
    uint32_t a;
    asm("{ .reg .u64 t; cvta.to.shared.u64 t, %1; cvt.u32.u64 %0, t; }"
        : "=r"(a) : "l"(p));
    return a;
}

__device__ __forceinline__ float sample_loss(const float x[NCLS], int tgt)
{
    float d[NCLS];
    float w = x[1];
    d[9] = fmaf(U9p, w, B9p * x[9]); w += x[9];
    d[8] = fmaf(U8p, w, B8p * x[8]); w += x[8];
    d[7] = fmaf(U7p, w, B7p * x[7]); w += x[7];
    d[6] = fmaf(U6p, w, B6p * x[6]); w += x[6];
    d[5] = fmaf(U5p, w, B5p * x[5]); w += x[5];
    d[4] = fmaf(U4p, w, B4p * x[4]); w += x[4];
    d[3] = fmaf(U3p, w, B3p * x[3]); w += x[3];
    d[2] = fmaf(U2p, w, B2p * x[2]); w += x[2];
    d[0] = U0p * w;
    d[1] = x[0];                           // row1 = e0, |e0| = 1

    float nsq = 0.f;
#pragma unroll
    for (int k = 0; k < NCLS; k++) nsq = fmaf(x[k], x[k], nsq);
    const float inv1 = rsqrtf(nsq);

    float m[NCLS];
    float adot = d[0];
#pragma unroll
    for (int c = 0; c < NCLS; c++) {
        const bool p = (tgt == c);
        m[c] = p ? -1e30f : d[c];
        if (c > 0) adot = p ? d[c] : adot;
    }
    const float m01 = fmaxf(m[0], m[1]), m23 = fmaxf(m[2], m[3]);
    const float m45 = fmaxf(m[4], m[5]), m67 = fmaxf(m[6], m[7]);
    const float m89 = fmaxf(m[8], m[9]);
    const float best = fmaxf(fmaxf(fmaxf(m01, m23), fmaxf(m45, m67)), m89);

    return fmaxf(fmaf(best, inv1, -0.5f), 0.f) +
           fmaxf(fmaf(-adot, inv1, 0.5f), 0.f);
}

__global__ __launch_bounds__(TPB, 2)
void margin_loss_kernel(const float* __restrict__ x1,
                        const int*   __restrict__ target,
                        int B, float invB, float* __restrict__ out)
{
    extern __shared__ char smem[];
    const int tid = threadIdx.x;
    const uint32_t smem_base = smem_u32(smem);

    // STAGES mbarriers at offsets 0,8,16,24 (tx-count completion, 1 arrival).
    if (tid == 0) {
#pragma unroll
        for (int s = 0; s < STAGES; s++)
            asm volatile("mbarrier.init.shared.b64 [%0], 1;"
                         :: "r"(smem_base + s * 8) : "memory");
    }
    __syncthreads();

    const int nTiles = B / TILE;
    const int nLocal = (blockIdx.x < nTiles)
                       ? (nTiles - blockIdx.x - 1) / gridDim.x + 1 : 0;

    // Prologue: fill pipeline.
    if (tid == 0) {
        const int pre = nLocal < STAGES ? nLocal : STAGES;
        for (int k = 0; k < pre; k++) {
            const int g = blockIdx.x + k * gridDim.x;   // global tile id
            const uint32_t mb = smem_base + k * 8;
            const uint32_t xd = smem_base + SMEM_DATA_OFF + k * STAGE_BYTES;
            asm volatile("mbarrier.arrive.expect_tx.shared.b64 _, [%0], %1;"
                         :: "r"(mb), "r"((uint32_t)STAGE_BYTES) : "memory");
            asm volatile("cp.async.bulk.shared::cta.global.mbarrier::complete_tx::bytes [%0], [%1], %2, [%3];"
                         :: "r"(xd), "l"(x1 + (size_t)g * TILE * NCLS),
                            "r"((uint32_t)X_BYTES), "r"(mb) : "memory");
            asm volatile("cp.async.bulk.shared::cta.global.mbarrier::complete_tx::bytes [%0], [%1], %2, [%3];"
                         :: "r"(xd + X_BYTES), "l"(target + (size_t)g * TILE),
                            "r"((uint32_t)T_BYTES), "r"(mb) : "memory");
        }
    }

    float acc = 0.f;

    for (int k = 0; k < nLocal; k++) {
        const int s  = k & (STAGES - 1);
        const uint32_t ph = (uint32_t)((k / STAGES) & 1);
        const uint32_t mb = smem_base + s * 8;

        // Acquire-wait for stage data.
        asm volatile(
            "{\n\t.reg .pred P;\n"
            "WLP_%=:\n\t"
            "mbarrier.try_wait.parity.acquire.cta.shared::cta.b64 P, [%0], %1, 0x989680;\n\t"
            "@P bra.uni WDN_%=;\n\t"
            "bra.uni WLP_%=;\n"
            "WDN_%=:\n\t}"
            :: "r"(mb), "r"(ph) : "memory");

        // Copy this thread's 40B sample to registers IMMEDIATELY (5x LDS.64,
        // 8-aligned; conflict-free), then release the stage for refill BEFORE
        // computing -> compute overlaps the in-flight TMA instead of sitting
        // inside the pipeline round-trip.
        const char* xsm = smem + SMEM_DATA_OFF + s * STAGE_BYTES + 40 * tid;
        const float2* xp = reinterpret_cast<const float2*>(xsm);
        const float2 v0 = xp[0], v1 = xp[1], v2 = xp[2], v3 = xp[3], v4 = xp[4];
        const int tgt = *reinterpret_cast<const int*>(
            smem + SMEM_DATA_OFF + s * STAGE_BYTES + X_BYTES + 4 * tid);

        __syncthreads();   // all threads hold their data in registers
        if (tid == 0 && k + STAGES < nLocal) {
            const int g = blockIdx.x + (k + STAGES) * gridDim.x;
            const uint32_t xd = smem_base + SMEM_DATA_OFF + s * STAGE_BYTES;
            asm volatile("mbarrier.arrive.expect_tx.shared.b64 _, [%0], %1;"
                         :: "r"(mb), "r"((uint32_t)STAGE_BYTES) : "memory");
            asm volatile("cp.async.bulk.shared::cta.global.mbarrier::complete_tx::bytes [%0], [%1], %2, [%3];"
                         :: "r"(xd), "l"(x1 + (size_t)g * TILE * NCLS),
                            "r"((uint32_t)X_BYTES), "r"(mb) : "memory");
            asm volatile("cp.async.bulk.shared::cta.global.mbarrier::complete_tx::bytes [%0], [%1], %2, [%3];"
                         :: "r"(xd + X_BYTES), "l"(target + (size_t)g * TILE),
                            "r"((uint32_t)T_BYTES), "r"(mb) : "memory");
        }

        const float x[NCLS] = {v0.x, v0.y, v1.x, v1.y, v2.x,
                               v2.y, v3.x, v3.y, v4.x, v4.y};
        acc += sample_loss(x, tgt);
    }

    // Tail: B - nTiles*TILE samples (256 for B=4M), direct global loads.
    const int base = nTiles * TILE;
    const int rem  = B - base;
    if (blockIdx.x == 0 && tid < rem) {
        const float* xr = x1 + (size_t)(base + tid) * NCLS;
        float xt[NCLS];
        const float2* xp = reinterpret_cast<const float2*>(xr);
        const float2 v0 = xp[0], v1 = xp[1], v2 = xp[2], v3 = xp[3], v4 = xp[4];
        xt[0]=v0.x; xt[1]=v0.y; xt[2]=v1.x; xt[3]=v1.y; xt[4]=v2.x;
        xt[5]=v2.y; xt[6]=v3.x; xt[7]=v3.y; xt[8]=v4.x; xt[9]=v4.y;
        acc += sample_loss(xt, target[base + tid]);
    }

    // Deterministic block reduction.
    __shared__ float red[TPB];
    red[tid] = acc;
    __syncthreads();
#pragma unroll
    for (int s = TPB / 2; s > 0; s >>= 1) {
        if (tid < s) red[tid] += red[tid + s];
        __syncthreads();
    }

    // Fused final reduction: last block sums partials in fixed order.
    __shared__ bool s_last;
    if (tid == 0) {
        g_partials[blockIdx.x] = red[0];
        __threadfence();
        const int old = atomicAdd(&g_counter, 1);
        s_last = (old == NBLOCKS - 1);
    }
    __syncthreads();

    if (s_last) {
        __threadfence();
        float a = (tid < NBLOCKS) ? g_partials[tid] : 0.f;
        red[tid] = a;
        __syncthreads();
#pragma unroll
        for (int s = TPB / 2; s > 0; s >>= 1) {
            if (tid < s) red[tid] += red[tid + s];
            __syncthreads();
        }
        if (tid == 0) {
            g_counter = 0;          // reset for graph replay
            out[0] = red[0] * invB;
        }
    }
}

extern "C" void kernel_launch(void* const* d_in, const int* in_sizes, int n_in,
                              void* d_out, int out_size)
{
    const float* x1     = (const float*)d_in[0];
    const int*   target = (const int*)  d_in[1];
    float* out = (float*)d_out;

    const int B = in_sizes[0] / NCLS;

    static bool attr_set = false;
    if (!attr_set) {
        cudaFuncSetAttribute(margin_loss_kernel,
                             cudaFuncAttributeMaxDynamicSharedMemorySize,
                             SMEM_TOTAL);
        attr_set = true;
    }

    margin_loss_kernel<<<NBLOCKS, TPB, SMEM_TOTAL>>>(x1, target, B,
                                                     1.0f / (float)B, out);
}